// round 6
// baseline (speedup 1.0000x reference)
#include <cuda_runtime.h>
#include <cuda_bf16.h>
#include <cstdint>

// HarmonicLowering: x (8,32,256,512) f32 -> out (8,128,256,512) f32
//   out[b, k*32+c, i, t] = w*x[b,c,idx,t] + (1-w)*x[b,c,idx1,t]
//   prod=i*(k+1), idx=prod>>2, rem=prod&3, w=1-rem/4, idx1=min(idx+1,255)
//
// R5: one warp per PAIR of consecutive i rows (same bc,k -> warp-uniform).
// Both rows' g0 loads (8x LDG.128) front-batched, conditional g1 loads next,
// then 8 compute+streaming-stores. Doubles per-warp MLP so each warp keeps
// issuing while a row's loads are outstanding. Grid ordered so all rows
// reading one (b,c) plane are contiguous -> input L2-resident, read ~1x.

static constexpr int BATCH = 8;
static constexpr int C     = 32;
static constexpr int FREQ  = 256;
static constexpr int TIME  = 512;
static constexpr int T4    = TIME / 4;          // 128 float4 per row
static constexpr int K     = 4;

static constexpr int THREADS = 256;             // 8 warps = 8 row-pairs/block
static constexpr int PAIRS_TOTAL = BATCH * C * K * (FREQ / 2);  // 131072
static constexpr int NBLOCKS = PAIRS_TOTAL / 8;                 // 16384

__device__ __forceinline__ void lerp_store(float4* po, const float4 g0[4],
                                           const float4* p1, float w)
{
    float4 g1[4];
#pragma unroll
    for (int j = 0; j < 4; j++) g1[j] = __ldg(p1 + j * 32);
    const float w1 = 1.0f - w;
#pragma unroll
    for (int j = 0; j < 4; j++) {
        float4 o;
        o.x = w * g0[j].x + w1 * g1[j].x;
        o.y = w * g0[j].y + w1 * g1[j].y;
        o.z = w * g0[j].z + w1 * g1[j].z;
        o.w = w * g0[j].w + w1 * g1[j].w;
        __stcs(po + j * 32, o);
    }
}

__global__ __launch_bounds__(THREADS) void harmonic_lowering_kernel(
    const float4* __restrict__ in, float4* __restrict__ out)
{
    const int lane = threadIdx.x & 31;
    const int wp   = blockIdx.x * 8 + (threadIdx.x >> 5);   // pair id

    // pair id = ((bc*K + k)*(FREQ/2) + m);  rows i0=2m, i1=2m+1
    int m = wp & (FREQ / 2 - 1);
    int r = wp >> 7;
    int k = r & (K - 1);
    r >>= 2;                         // bc = b*C + c in [0,256)

    const int i0 = 2 * m;
    const int prod0 = i0 * (k + 1);
    const int prod1 = prod0 + (k + 1);
    const int idx0 = prod0 >> 2, rem0 = prod0 & 3;
    const int idx1 = prod1 >> 2, rem1 = prod1 & 3;

    const float4* base = in + ((unsigned)r << 15);          // bc * 32768
    const float4* p0a = base + (idx0 << 7) + lane;
    const float4* p0b = base + (idx1 << 7) + lane;

    const int b = r >> 5, c = r & (C - 1);
    float4* po = out + (((((unsigned)b * (K * C) + (unsigned)k * C + c) << 8)
                         + i0) << 7) + lane;

    // Front-batch both rows' primary loads: 8 independent LDG.128
    float4 a0[4], b0[4];
#pragma unroll
    for (int j = 0; j < 4; j++) a0[j] = __ldg(p0a + j * 32);
#pragma unroll
    for (int j = 0; j < 4; j++) b0[j] = __ldg(p0b + j * 32);

    // Row i0
    if (rem0) {
        int n0 = idx0 + 1; if (n0 > FREQ - 1) n0 = FREQ - 1;
        lerp_store(po, a0, base + (n0 << 7) + lane, 1.0f - 0.25f * (float)rem0);
    } else {
#pragma unroll
        for (int j = 0; j < 4; j++) __stcs(po + j * 32, a0[j]);
    }

    // Row i1
    float4* po1 = po + T4;
    if (rem1) {
        int n1 = idx1 + 1; if (n1 > FREQ - 1) n1 = FREQ - 1;
        lerp_store(po1, b0, base + (n1 << 7) + lane, 1.0f - 0.25f * (float)rem1);
    } else {
#pragma unroll
        for (int j = 0; j < 4; j++) __stcs(po1 + j * 32, b0[j]);
    }
}

extern "C" void kernel_launch(void* const* d_in, const int* in_sizes, int n_in,
                              void* d_out, int out_size)
{
    const float4* in = (const float4*)d_in[0];
    float4* out = (float4*)d_out;
    harmonic_lowering_kernel<<<NBLOCKS, THREADS>>>(in, out);
}